// round 4
// baseline (speedup 1.0000x reference)
#include <cuda_runtime.h>
#include <math.h>

#define Nn 4
#define Cc 512
#define Ll 4096
#define Dd 256
#define Kk 8192
#define Pp (Nn*Ll)               // 16384 positions
#define OUT_Y ((size_t)Nn*Cc*Ll) // 8388608
#define OUT_LOSS (OUT_Y + Pp)    // 8404992

// -------- device scratch (static, no allocation) --------
__device__ float g_Win[Dd*Cc];           // 512 KB
__device__ float g_Wout[Cc*Dd];          // 512 KB
__device__ float g_Wq[(size_t)Kk*Cc];    // 16 MB  (codebook @ W_out^T)
__device__ float g_invn[Kk];             // 1/max(||cb_k||, eps)
__device__ float g_zet[(size_t)Pp*Dd];   // 16 MB  z_e transposed: [pos][d]
__device__ int   g_idx[Pp];
__device__ float g_losspart[Pp/64];      // per-search-block partial loss

// ================= prep: weight_norm rows =================
__global__ void __launch_bounds__(128) prep_wn_kernel(
    const float* __restrict__ v, const float* __restrict__ g, int cols, int sel)
{
    float* W = sel ? g_Wout : g_Win;
    const int r = blockIdx.x, tid = threadIdx.x;
    float s = 0.f;
    for (int c = tid; c < cols; c += 128) { float t = v[(size_t)r*cols + c]; s = fmaf(t, t, s); }
    #pragma unroll
    for (int m = 16; m; m >>= 1) s += __shfl_xor_sync(0xffffffffu, s, m);
    __shared__ float red[4];
    if ((tid & 31) == 0) red[tid >> 5] = s;
    __syncthreads();
    s = red[0] + red[1] + red[2] + red[3];
    const float scale = g[r] / sqrtf(s);
    for (int c = tid; c < cols; c += 128)
        W[(size_t)r*cols + c] = v[(size_t)r*cols + c] * scale;
}

// ================= prep: codebook inverse norms =================
__global__ void __launch_bounds__(128) prep_cbinv_kernel(const float* __restrict__ cb)
{
    const int r = blockIdx.x, tid = threadIdx.x;
    float s = 0.f;
    for (int c = tid; c < Dd; c += 128) { float t = cb[(size_t)r*Dd + c]; s = fmaf(t, t, s); }
    #pragma unroll
    for (int m = 16; m; m >>= 1) s += __shfl_xor_sync(0xffffffffu, s, m);
    __shared__ float red[4];
    if ((tid & 31) == 0) red[tid >> 5] = s;
    __syncthreads();
    if (tid == 0) {
        s = red[0] + red[1] + red[2] + red[3];
        g_invn[r] = 1.f / fmaxf(sqrtf(s), 1e-8f);
    }
}

// ================= z_e GEMM: zet[n*L+l][d] = sum_c Win[d][c]*x[n][c][l] + in_b[d] =================
__global__ void __launch_bounds__(128) ze_gemm_kernel(
    const float* __restrict__ x, const float* __restrict__ inb)
{
    __shared__ float xs[32][64];    // [c'][l']
    __shared__ float ws[32][68];    // [c'][d'] padded
    const int tid = threadIdx.x, ty = tid >> 4, tx = tid & 15;
    const int l0 = blockIdx.x * 64, d0 = blockIdx.y * 64, n = blockIdx.z;
    const float* xn = x + (size_t)n * Cc * Ll;
    float acc[8][4];
    #pragma unroll
    for (int i = 0; i < 8; i++)
        #pragma unroll
        for (int j = 0; j < 4; j++) acc[i][j] = 0.f;

    for (int c0 = 0; c0 < Cc; c0 += 32) {
        #pragma unroll
        for (int i = tid; i < 32*64; i += 128) { int c = i >> 6, l = i & 63; xs[c][l] = xn[(size_t)(c0 + c)*Ll + l0 + l]; }
        #pragma unroll
        for (int i = tid; i < 64*32; i += 128) { int d = i >> 5, c = i & 31; ws[c][d] = g_Win[(d0 + d)*Cc + c0 + c]; }
        __syncthreads();
        #pragma unroll 8
        for (int c = 0; c < 32; c++) {
            float4 a0 = *(const float4*)&xs[c][ty*8];
            float4 a1 = *(const float4*)&xs[c][ty*8 + 4];
            float4 b  = *(const float4*)&ws[c][tx*4];
            float av[8] = {a0.x,a0.y,a0.z,a0.w,a1.x,a1.y,a1.z,a1.w};
            float bv[4] = {b.x,b.y,b.z,b.w};
            #pragma unroll
            for (int i = 0; i < 8; i++)
                #pragma unroll
                for (int j = 0; j < 4; j++) acc[i][j] = fmaf(av[i], bv[j], acc[i][j]);
        }
        __syncthreads();
    }
    const float b0 = inb[d0 + tx*4 + 0], b1 = inb[d0 + tx*4 + 1];
    const float b2 = inb[d0 + tx*4 + 2], b3 = inb[d0 + tx*4 + 3];
    #pragma unroll
    for (int i = 0; i < 8; i++) {
        int l = l0 + ty*8 + i;
        float4 o = make_float4(acc[i][0]+b0, acc[i][1]+b1, acc[i][2]+b2, acc[i][3]+b3);
        *(float4*)&g_zet[((size_t)(n*Ll + l))*Dd + d0 + tx*4] = o;
    }
}

// ================= Wq GEMM: Wq[k][c] = sum_d cb[k][d]*Wout[c][d] =================
__global__ void __launch_bounds__(128) wq_gemm_kernel(const float* __restrict__ cb)
{
    __shared__ float as_[32][68];   // [d'][k']
    __shared__ float bs_[32][68];   // [d'][c']
    const int tid = threadIdx.x, ty = tid >> 4, tx = tid & 15;
    const int k0 = blockIdx.x * 64, c0 = blockIdx.y * 64;
    float acc[8][4];
    #pragma unroll
    for (int i = 0; i < 8; i++)
        #pragma unroll
        for (int j = 0; j < 4; j++) acc[i][j] = 0.f;

    for (int d0 = 0; d0 < Dd; d0 += 32) {
        #pragma unroll
        for (int i = tid; i < 64*32; i += 128) { int k = i >> 5, d = i & 31; as_[d][k] = cb[(size_t)(k0 + k)*Dd + d0 + d]; }
        #pragma unroll
        for (int i = tid; i < 64*32; i += 128) { int c = i >> 5, d = i & 31; bs_[d][c] = g_Wout[(c0 + c)*Dd + d0 + d]; }
        __syncthreads();
        #pragma unroll 8
        for (int d = 0; d < 32; d++) {
            float4 a0 = *(const float4*)&as_[d][ty*8];
            float4 a1 = *(const float4*)&as_[d][ty*8 + 4];
            float4 b  = *(const float4*)&bs_[d][tx*4];
            float av[8] = {a0.x,a0.y,a0.z,a0.w,a1.x,a1.y,a1.z,a1.w};
            float bv[4] = {b.x,b.y,b.z,b.w};
            #pragma unroll
            for (int i = 0; i < 8; i++)
                #pragma unroll
                for (int j = 0; j < 4; j++) acc[i][j] = fmaf(av[i], bv[j], acc[i][j]);
        }
        __syncthreads();
    }
    #pragma unroll
    for (int i = 0; i < 8; i++) {
        int k = k0 + ty*8 + i;
        float4 o = make_float4(acc[i][0], acc[i][1], acc[i][2], acc[i][3]);
        *(float4*)&g_Wq[(size_t)k*Cc + c0 + tx*4] = o;
    }
}

// ================= fused search: argmax cos-sim + loss + index outputs =================
// block = 64 consecutive positions (same n). ze tile resident in smem (transposed),
// codebook streamed in 64-code x 32-d chunks with register prefetch.
__global__ void __launch_bounds__(128) search_kernel(
    const float* __restrict__ cb, float* __restrict__ out)
{
    extern __shared__ float dynsm[];
    float (*ze)[64]  = (float(*)[64])dynsm;              // [256 d][64 pos]
    float (*cbs)[68] = (float(*)[68])(dynsm + 256*64);   // [32 d][64 code] padded
    __shared__ int   sidx[64];
    __shared__ float lred[4];

    const int tid = threadIdx.x, ty = tid >> 4, tx = tid & 15;
    const int p0 = blockIdx.x * 64;

    for (int i = tid; i < 64*256; i += 128) {
        int pos = i >> 8, d = i & 255;
        ze[d][pos] = g_zet[(size_t)(p0 + pos)*Dd + d];
    }
    __syncthreads();

    float best[8]; int bidx[8];
    #pragma unroll
    for (int i = 0; i < 8; i++) { best[i] = -3.4e38f; bidx[i] = 0; }

    // prefetch first chunk (k0=0, dt=0)
    float4 pre[4];
    #pragma unroll
    for (int j = 0; j < 4; j++) {
        int f = tid + 128*j; int kk = f >> 3, d4 = f & 7;
        pre[j] = *(const float4*)&cb[(size_t)kk*Dd + d4*4];
    }

    for (int k0 = 0; k0 < Kk; k0 += 64) {
        float acc[8][4];
        #pragma unroll
        for (int i = 0; i < 8; i++)
            #pragma unroll
            for (int j = 0; j < 4; j++) acc[i][j] = 0.f;

        for (int dt = 0; dt < Dd; dt += 32) {
            // commit prefetched chunk to smem (transposed)
            #pragma unroll
            for (int j = 0; j < 4; j++) {
                int f = tid + 128*j; int kk = f >> 3, d4 = f & 7;
                cbs[d4*4 + 0][kk] = pre[j].x;
                cbs[d4*4 + 1][kk] = pre[j].y;
                cbs[d4*4 + 2][kk] = pre[j].z;
                cbs[d4*4 + 3][kk] = pre[j].w;
            }
            __syncthreads();
            // issue next chunk's global loads (overlap with compute)
            int ndt = dt + 32, nk0 = k0;
            if (ndt == Dd) { ndt = 0; nk0 = k0 + 64; }
            if (nk0 < Kk) {
                #pragma unroll
                for (int j = 0; j < 4; j++) {
                    int f = tid + 128*j; int kk = f >> 3, d4 = f & 7;
                    pre[j] = *(const float4*)&cb[(size_t)(nk0 + kk)*Dd + ndt + d4*4];
                }
            }
            #pragma unroll 8
            for (int d = 0; d < 32; ++d) {
                float4 a0 = *(const float4*)&ze[dt + d][ty*8];
                float4 a1 = *(const float4*)&ze[dt + d][ty*8 + 4];
                float4 b  = *(const float4*)&cbs[d][tx*4];
                float av[8] = {a0.x,a0.y,a0.z,a0.w,a1.x,a1.y,a1.z,a1.w};
                float bv[4] = {b.x,b.y,b.z,b.w};
                #pragma unroll
                for (int i = 0; i < 8; i++)
                    #pragma unroll
                    for (int j = 0; j < 4; j++) acc[i][j] = fmaf(av[i], bv[j], acc[i][j]);
            }
            __syncthreads();
        }
        // scale by inverse codebook norm, running argmax (ties -> lowest k)
        #pragma unroll
        for (int j = 0; j < 4; j++) {
            int k = k0 + tx*4 + j;
            float s = g_invn[k];
            #pragma unroll
            for (int i = 0; i < 8; i++) {
                float v = acc[i][j] * s;
                if (v > best[i]) { best[i] = v; bidx[i] = k; }
            }
        }
    }

    // reduce over the 16 code-lanes sharing each position group
    #pragma unroll
    for (int i = 0; i < 8; i++) {
        float b = best[i]; int ix = bidx[i];
        #pragma unroll
        for (int m = 1; m < 16; m <<= 1) {
            float ob = __shfl_xor_sync(0xffffffffu, b, m);
            int   oi = __shfl_xor_sync(0xffffffffu, ix, m);
            if (ob > b || (ob == b && oi < ix)) { b = ob; ix = oi; }
        }
        if (tx == 0) {
            int pos = ty*8 + i;
            sidx[pos] = ix;
            g_idx[p0 + pos] = ix;
            out[OUT_Y + p0 + pos] = (float)ix;
        }
    }
    __syncthreads();

    // fused VQ loss: sum over (pos,d) of (cb[idx] - z_e)^2   (cb_loss == cm_loss)
    float ls = 0.f;
    for (int i = tid; i < 64*256; i += 128) {
        int pos = i >> 8, d = i & 255;
        float diff = cb[(size_t)sidx[pos]*Dd + d] - ze[d][pos];
        ls = fmaf(diff, diff, ls);
    }
    #pragma unroll
    for (int m = 16; m; m >>= 1) ls += __shfl_xor_sync(0xffffffffu, ls, m);
    if ((tid & 31) == 0) lred[tid >> 5] = ls;
    __syncthreads();
    if (tid == 0) g_losspart[blockIdx.x] = lred[0] + lred[1] + lred[2] + lred[3];
}

// ================= y gather: y[n][c][l] = Wq[idx[n,l]][c] + out_b[c] =================
__global__ void __launch_bounds__(256) gather_kernel(
    const float* __restrict__ outb, float* __restrict__ out)
{
    extern __shared__ float sm[];   // [32][513]
    __shared__ int sidx[32];
    const int tid = threadIdx.x;
    const int l0 = blockIdx.x * 32, n = blockIdx.y;
    if (tid < 32) sidx[tid] = g_idx[n*Ll + l0 + tid];
    __syncthreads();
    for (int i = tid; i < 32*512; i += 256) {
        int l = i >> 9, c = i & 511;
        sm[l*513 + c] = g_Wq[(size_t)sidx[l]*Cc + c];
    }
    __syncthreads();
    for (int i = tid; i < 512*32; i += 256) {
        int c = i >> 5, l = i & 31;
        out[((size_t)n*Cc + c)*Ll + l0 + l] = sm[l*513 + c] + __ldg(&outb[c]);
    }
}

// ================= finalize losses =================
__global__ void finalize_kernel(float* __restrict__ out)
{
    const int tid = threadIdx.x;            // 128 threads: 4 warps, one per n
    const int n = tid >> 5, lane = tid & 31;
    float s = g_losspart[n*64 + lane] + g_losspart[n*64 + 32 + lane];
    #pragma unroll
    for (int m = 16; m; m >>= 1) s += __shfl_xor_sync(0xffffffffu, s, m);
    if (lane == 0) {
        float v = s * (1.0f / (float)(Dd * Ll));
        out[OUT_LOSS + n]     = v;   // cb_loss
        out[OUT_LOSS + 4 + n] = v;   // cm_loss (numerically identical)
    }
}

// ================= launch =================
extern "C" void kernel_launch(void* const* d_in, const int* in_sizes, int n_in,
                              void* d_out, int out_size)
{
    (void)in_sizes; (void)n_in; (void)out_size;
    const float* x    = (const float*)d_in[0];
    const float* vin  = (const float*)d_in[1];
    const float* gin  = (const float*)d_in[2];
    const float* bin  = (const float*)d_in[3];
    const float* vout = (const float*)d_in[4];
    const float* gout = (const float*)d_in[5];
    const float* bout = (const float*)d_in[6];
    const float* cb   = (const float*)d_in[7];
    float* out = (float*)d_out;

    const int SEARCH_SMEM = (256*64 + 32*68) * 4;   // 74240 B
    const int GATHER_SMEM = 32*513*4;               // 65664 B
    cudaFuncSetAttribute(search_kernel, cudaFuncAttributeMaxDynamicSharedMemorySize, SEARCH_SMEM);
    cudaFuncSetAttribute(gather_kernel, cudaFuncAttributeMaxDynamicSharedMemorySize, GATHER_SMEM);

    prep_wn_kernel<<<Dd, 128>>>(vin, gin, Cc, 0);
    prep_wn_kernel<<<Cc, 128>>>(vout, gout, Dd, 1);
    prep_cbinv_kernel<<<Kk, 128>>>(cb);
    ze_gemm_kernel<<<dim3(Ll/64, Dd/64, Nn), 128>>>(x, bin);
    wq_gemm_kernel<<<dim3(Kk/64, Cc/64), 128>>>(cb);
    search_kernel<<<Pp/64, 128, SEARCH_SMEM>>>(cb, out);
    gather_kernel<<<dim3(Ll/32, Nn), 256, GATHER_SMEM>>>(bout, out);
    finalize_kernel<<<1, 128>>>(out);
}

// round 5
// speedup vs baseline: 1.1645x; 1.1645x over previous
#include <cuda_runtime.h>
#include <math.h>

#define Nn 4
#define Cc 512
#define Ll 4096
#define Dd 256
#define Kk 8192
#define Pp (Nn*Ll)               // 16384 positions
#define OUT_Y ((size_t)Nn*Cc*Ll) // 8388608
#define OUT_LOSS (OUT_Y + Pp)    // 8404992

typedef unsigned long long u64;

// packed fp32x2 FMA (sm_100+/sm_103a): 2 IEEE fp32 FMAs per instruction
#define FMA2(d, a, b, c) \
    asm("fma.rn.f32x2 %0, %1, %2, %3;" : "=l"(d) : "l"(a), "l"(b), "l"(c))
#define DUP2(d, s) \
    asm("mov.b64 %0, {%1, %1};" : "=l"(d) : "f"(s))

__device__ __forceinline__ float lo32f(u64 v) { return __uint_as_float((unsigned)(v & 0xffffffffu)); }
__device__ __forceinline__ float hi32f(u64 v) { return __uint_as_float((unsigned)(v >> 32)); }

// -------- device scratch (static, no allocation) --------
__device__ float g_Win[Dd*Cc];           // 512 KB
__device__ float g_Wout[Cc*Dd];          // 512 KB
__device__ float g_Wq[(size_t)Kk*Cc];    // 16 MB  (codebook @ W_out^T)
__device__ float g_invn[Kk];             // 1/max(||cb_k||, eps)
__device__ float g_zet[(size_t)Pp*Dd];   // 16 MB  z_e transposed: [pos][d]
__device__ int   g_idx[Pp];
__device__ float g_losspart[Pp/64];      // per-search-block partial loss

// ================= prep: weight_norm rows =================
__global__ void __launch_bounds__(128) prep_wn_kernel(
    const float* __restrict__ v, const float* __restrict__ g, int cols, int sel)
{
    float* W = sel ? g_Wout : g_Win;
    const int r = blockIdx.x, tid = threadIdx.x;
    float s = 0.f;
    for (int c = tid; c < cols; c += 128) { float t = v[(size_t)r*cols + c]; s = fmaf(t, t, s); }
    #pragma unroll
    for (int m = 16; m; m >>= 1) s += __shfl_xor_sync(0xffffffffu, s, m);
    __shared__ float red[4];
    if ((tid & 31) == 0) red[tid >> 5] = s;
    __syncthreads();
    s = red[0] + red[1] + red[2] + red[3];
    const float scale = g[r] / sqrtf(s);
    for (int c = tid; c < cols; c += 128)
        W[(size_t)r*cols + c] = v[(size_t)r*cols + c] * scale;
}

// ================= prep: codebook inverse norms =================
__global__ void __launch_bounds__(128) prep_cbinv_kernel(const float* __restrict__ cb)
{
    const int r = blockIdx.x, tid = threadIdx.x;
    float s = 0.f;
    for (int c = tid; c < Dd; c += 128) { float t = cb[(size_t)r*Dd + c]; s = fmaf(t, t, s); }
    #pragma unroll
    for (int m = 16; m; m >>= 1) s += __shfl_xor_sync(0xffffffffu, s, m);
    __shared__ float red[4];
    if ((tid & 31) == 0) red[tid >> 5] = s;
    __syncthreads();
    if (tid == 0) {
        s = red[0] + red[1] + red[2] + red[3];
        g_invn[r] = 1.f / fmaxf(sqrtf(s), 1e-8f);
    }
}

// 16 packed FMAs for an 8(pos,paired)x4 microtile step
#define MICRO_FMA2(acc2, aA, aB, b4)                                     \
    do {                                                                 \
        u64 bb0, bb1, bb2, bb3;                                          \
        DUP2(bb0, (b4).x); DUP2(bb1, (b4).y);                            \
        DUP2(bb2, (b4).z); DUP2(bb3, (b4).w);                            \
        FMA2(acc2[0][0], (aA).x, bb0, acc2[0][0]);                       \
        FMA2(acc2[0][1], (aA).x, bb1, acc2[0][1]);                       \
        FMA2(acc2[0][2], (aA).x, bb2, acc2[0][2]);                       \
        FMA2(acc2[0][3], (aA).x, bb3, acc2[0][3]);                       \
        FMA2(acc2[1][0], (aA).y, bb0, acc2[1][0]);                       \
        FMA2(acc2[1][1], (aA).y, bb1, acc2[1][1]);                       \
        FMA2(acc2[1][2], (aA).y, bb2, acc2[1][2]);                       \
        FMA2(acc2[1][3], (aA).y, bb3, acc2[1][3]);                       \
        FMA2(acc2[2][0], (aB).x, bb0, acc2[2][0]);                       \
        FMA2(acc2[2][1], (aB).x, bb1, acc2[2][1]);                       \
        FMA2(acc2[2][2], (aB).x, bb2, acc2[2][2]);                       \
        FMA2(acc2[2][3], (aB).x, bb3, acc2[2][3]);                       \
        FMA2(acc2[3][0], (aB).y, bb0, acc2[3][0]);                       \
        FMA2(acc2[3][1], (aB).y, bb1, acc2[3][1]);                       \
        FMA2(acc2[3][2], (aB).y, bb2, acc2[3][2]);                       \
        FMA2(acc2[3][3], (aB).y, bb3, acc2[3][3]);                       \
    } while (0)

// ================= z_e GEMM: zet[n*L+l][d] = sum_c Win[d][c]*x[n][c][l] + in_b[d] =================
__global__ void __launch_bounds__(128) ze_gemm_kernel(
    const float* __restrict__ x, const float* __restrict__ inb)
{
    __shared__ float xs[32][64];    // [c'][l']
    __shared__ float ws[32][68];    // [c'][d'] padded (68*4=272B rows, 16B aligned)
    const int tid = threadIdx.x, ty = tid >> 4, tx = tid & 15;
    const int l0 = blockIdx.x * 64, d0 = blockIdx.y * 64, n = blockIdx.z;
    const float* xn = x + (size_t)n * Cc * Ll;
    u64 acc2[4][4];
    #pragma unroll
    for (int i = 0; i < 4; i++)
        #pragma unroll
        for (int j = 0; j < 4; j++) acc2[i][j] = 0ull;

    for (int c0 = 0; c0 < Cc; c0 += 32) {
        #pragma unroll
        for (int i = tid; i < 32*64; i += 128) { int c = i >> 6, l = i & 63; xs[c][l] = xn[(size_t)(c0 + c)*Ll + l0 + l]; }
        #pragma unroll
        for (int i = tid; i < 64*32; i += 128) { int d = i >> 5, c = i & 31; ws[c][d] = g_Win[(d0 + d)*Cc + c0 + c]; }
        __syncthreads();
        #pragma unroll 8
        for (int c = 0; c < 32; c++) {
            ulonglong2 aA = *(const ulonglong2*)&xs[c][ty*8];      // pos pairs 0,1
            ulonglong2 aB = *(const ulonglong2*)&xs[c][ty*8 + 4];  // pos pairs 2,3
            float4 b = *(const float4*)&ws[c][tx*4];
            MICRO_FMA2(acc2, aA, aB, b);
        }
        __syncthreads();
    }
    const float b0 = inb[d0 + tx*4 + 0], b1 = inb[d0 + tx*4 + 1];
    const float b2 = inb[d0 + tx*4 + 2], b3 = inb[d0 + tx*4 + 3];
    #pragma unroll
    for (int i2 = 0; i2 < 4; i2++) {
        #pragma unroll
        for (int h = 0; h < 2; h++) {
            int l = l0 + ty*8 + i2*2 + h;
            float4 o;
            o.x = (h ? hi32f(acc2[i2][0]) : lo32f(acc2[i2][0])) + b0;
            o.y = (h ? hi32f(acc2[i2][1]) : lo32f(acc2[i2][1])) + b1;
            o.z = (h ? hi32f(acc2[i2][2]) : lo32f(acc2[i2][2])) + b2;
            o.w = (h ? hi32f(acc2[i2][3]) : lo32f(acc2[i2][3])) + b3;
            *(float4*)&g_zet[((size_t)(n*Ll + l))*Dd + d0 + tx*4] = o;
        }
    }
}

// ================= Wq GEMM: Wq[k][c] = sum_d cb[k][d]*Wout[c][d] =================
__global__ void __launch_bounds__(128) wq_gemm_kernel(const float* __restrict__ cb)
{
    __shared__ float as_[32][68];   // [d'][k']
    __shared__ float bs_[32][68];   // [d'][c']
    const int tid = threadIdx.x, ty = tid >> 4, tx = tid & 15;
    const int k0 = blockIdx.x * 64, c0 = blockIdx.y * 64;
    u64 acc2[4][4];
    #pragma unroll
    for (int i = 0; i < 4; i++)
        #pragma unroll
        for (int j = 0; j < 4; j++) acc2[i][j] = 0ull;

    for (int d0 = 0; d0 < Dd; d0 += 32) {
        #pragma unroll
        for (int i = tid; i < 64*32; i += 128) { int k = i >> 5, d = i & 31; as_[d][k] = cb[(size_t)(k0 + k)*Dd + d0 + d]; }
        #pragma unroll
        for (int i = tid; i < 64*32; i += 128) { int c = i >> 5, d = i & 31; bs_[d][c] = g_Wout[(c0 + c)*Dd + d0 + d]; }
        __syncthreads();
        #pragma unroll 8
        for (int d = 0; d < 32; d++) {
            ulonglong2 aA = *(const ulonglong2*)&as_[d][ty*8];
            ulonglong2 aB = *(const ulonglong2*)&as_[d][ty*8 + 4];
            float4 b = *(const float4*)&bs_[d][tx*4];
            MICRO_FMA2(acc2, aA, aB, b);
        }
        __syncthreads();
    }
    #pragma unroll
    for (int i2 = 0; i2 < 4; i2++) {
        #pragma unroll
        for (int h = 0; h < 2; h++) {
            int k = k0 + ty*8 + i2*2 + h;
            float4 o;
            o.x = h ? hi32f(acc2[i2][0]) : lo32f(acc2[i2][0]);
            o.y = h ? hi32f(acc2[i2][1]) : lo32f(acc2[i2][1]);
            o.z = h ? hi32f(acc2[i2][2]) : lo32f(acc2[i2][2]);
            o.w = h ? hi32f(acc2[i2][3]) : lo32f(acc2[i2][3]);
            *(float4*)&g_Wq[(size_t)k*Cc + c0 + tx*4] = o;
        }
    }
}

// ================= fused search: argmax cos-sim + loss + index outputs =================
// block = 64 consecutive positions (same n). ze tile resident in smem (transposed),
// codebook streamed in 64-code x 32-d chunks with register prefetch.
// Mainloop uses packed fp32x2 FMA (2 positions per instruction, bit-exact fp32).
__global__ void __launch_bounds__(128) search_kernel(
    const float* __restrict__ cb, float* __restrict__ out)
{
    extern __shared__ float dynsm[];
    float (*ze)[64]  = (float(*)[64])dynsm;              // [256 d][64 pos]
    float (*cbs)[68] = (float(*)[68])(dynsm + 256*64);   // [32 d][64 code] padded
    __shared__ int   sidx[64];
    __shared__ float lred[4];

    const int tid = threadIdx.x, ty = tid >> 4, tx = tid & 15;
    const int p0 = blockIdx.x * 64;

    for (int i = tid; i < 64*256; i += 128) {
        int pos = i >> 8, d = i & 255;
        ze[d][pos] = g_zet[(size_t)(p0 + pos)*Dd + d];
    }
    __syncthreads();

    float best[8]; int bidx[8];
    #pragma unroll
    for (int i = 0; i < 8; i++) { best[i] = -3.4e38f; bidx[i] = 0; }

    // prefetch first chunk (k0=0, dt=0)
    float4 pre[4];
    #pragma unroll
    for (int j = 0; j < 4; j++) {
        int f = tid + 128*j; int kk = f >> 3, d4 = f & 7;
        pre[j] = *(const float4*)&cb[(size_t)kk*Dd + d4*4];
    }

    for (int k0 = 0; k0 < Kk; k0 += 64) {
        u64 acc2[4][4];
        #pragma unroll
        for (int i = 0; i < 4; i++)
            #pragma unroll
            for (int j = 0; j < 4; j++) acc2[i][j] = 0ull;

        for (int dt = 0; dt < Dd; dt += 32) {
            // commit prefetched chunk to smem (transposed)
            #pragma unroll
            for (int j = 0; j < 4; j++) {
                int f = tid + 128*j; int kk = f >> 3, d4 = f & 7;
                cbs[d4*4 + 0][kk] = pre[j].x;
                cbs[d4*4 + 1][kk] = pre[j].y;
                cbs[d4*4 + 2][kk] = pre[j].z;
                cbs[d4*4 + 3][kk] = pre[j].w;
            }
            __syncthreads();
            // issue next chunk's global loads (overlap with compute)
            int ndt = dt + 32, nk0 = k0;
            if (ndt == Dd) { ndt = 0; nk0 = k0 + 64; }
            if (nk0 < Kk) {
                #pragma unroll
                for (int j = 0; j < 4; j++) {
                    int f = tid + 128*j; int kk = f >> 3, d4 = f & 7;
                    pre[j] = *(const float4*)&cb[(size_t)(nk0 + kk)*Dd + ndt + d4*4];
                }
            }
            #pragma unroll 8
            for (int d = 0; d < 32; ++d) {
                ulonglong2 aA = *(const ulonglong2*)&ze[dt + d][ty*8];
                ulonglong2 aB = *(const ulonglong2*)&ze[dt + d][ty*8 + 4];
                float4 b = *(const float4*)&cbs[d][tx*4];
                MICRO_FMA2(acc2, aA, aB, b);
            }
            __syncthreads();
        }
        // scale by inverse codebook norm, running argmax (ties -> lowest k)
        #pragma unroll
        for (int j = 0; j < 4; j++) {
            int k = k0 + tx*4 + j;
            float s = g_invn[k];
            #pragma unroll
            for (int i2 = 0; i2 < 4; i2++) {
                float vlo = lo32f(acc2[i2][j]) * s;
                float vhi = hi32f(acc2[i2][j]) * s;
                if (vlo > best[i2*2])     { best[i2*2]     = vlo; bidx[i2*2]     = k; }
                if (vhi > best[i2*2 + 1]) { best[i2*2 + 1] = vhi; bidx[i2*2 + 1] = k; }
            }
        }
    }

    // reduce over the 16 code-lanes sharing each position group
    #pragma unroll
    for (int i = 0; i < 8; i++) {
        float b = best[i]; int ix = bidx[i];
        #pragma unroll
        for (int m = 1; m < 16; m <<= 1) {
            float ob = __shfl_xor_sync(0xffffffffu, b, m);
            int   oi = __shfl_xor_sync(0xffffffffu, ix, m);
            if (ob > b || (ob == b && oi < ix)) { b = ob; ix = oi; }
        }
        if (tx == 0) {
            int pos = ty*8 + i;
            sidx[pos] = ix;
            g_idx[p0 + pos] = ix;
            out[OUT_Y + p0 + pos] = (float)ix;
        }
    }
    __syncthreads();

    // fused VQ loss: sum over (pos,d) of (cb[idx] - z_e)^2   (cb_loss == cm_loss)
    float ls = 0.f;
    for (int i = tid; i < 64*256; i += 128) {
        int pos = i >> 8, d = i & 255;
        float diff = cb[(size_t)sidx[pos]*Dd + d] - ze[d][pos];
        ls = fmaf(diff, diff, ls);
    }
    #pragma unroll
    for (int m = 16; m; m >>= 1) ls += __shfl_xor_sync(0xffffffffu, ls, m);
    if ((tid & 31) == 0) lred[tid >> 5] = ls;
    __syncthreads();
    if (tid == 0) g_losspart[blockIdx.x] = lred[0] + lred[1] + lred[2] + lred[3];
}

// ================= y gather: y[n][c][l] = Wq[idx[n,l]][c] + out_b[c] =================
__global__ void __launch_bounds__(256) gather_kernel(
    const float* __restrict__ outb, float* __restrict__ out)
{
    extern __shared__ float sm[];   // [32][513]
    __shared__ int sidx[32];
    const int tid = threadIdx.x;
    const int l0 = blockIdx.x * 32, n = blockIdx.y;
    if (tid < 32) sidx[tid] = g_idx[n*Ll + l0 + tid];
    __syncthreads();
    for (int i = tid; i < 32*512; i += 256) {
        int l = i >> 9, c = i & 511;
        sm[l*513 + c] = g_Wq[(size_t)sidx[l]*Cc + c];
    }
    __syncthreads();
    for (int i = tid; i < 512*32; i += 256) {
        int c = i >> 5, l = i & 31;
        out[((size_t)n*Cc + c)*Ll + l0 + l] = sm[l*513 + c] + __ldg(&outb[c]);
    }
}

// ================= finalize losses =================
__global__ void finalize_kernel(float* __restrict__ out)
{
    const int tid = threadIdx.x;            // 128 threads: 4 warps, one per n
    const int n = tid >> 5, lane = tid & 31;
    float s = g_losspart[n*64 + lane] + g_losspart[n*64 + 32 + lane];
    #pragma unroll
    for (int m = 16; m; m >>= 1) s += __shfl_xor_sync(0xffffffffu, s, m);
    if (lane == 0) {
        float v = s * (1.0f / (float)(Dd * Ll));
        out[OUT_LOSS + n]     = v;   // cb_loss
        out[OUT_LOSS + 4 + n] = v;   // cm_loss (numerically identical)
    }
}

// ================= launch =================
extern "C" void kernel_launch(void* const* d_in, const int* in_sizes, int n_in,
                              void* d_out, int out_size)
{
    (void)in_sizes; (void)n_in; (void)out_size;
    const float* x    = (const float*)d_in[0];
    const float* vin  = (const float*)d_in[1];
    const float* gin  = (const float*)d_in[2];
    const float* bin  = (const float*)d_in[3];
    const float* vout = (const float*)d_in[4];
    const float* gout = (const float*)d_in[5];
    const float* bout = (const float*)d_in[6];
    const float* cb   = (const float*)d_in[7];
    float* out = (float*)d_out;

    const int SEARCH_SMEM = (256*64 + 32*68) * 4;   // 74240 B
    const int GATHER_SMEM = 32*513*4;               // 65664 B
    cudaFuncSetAttribute(search_kernel, cudaFuncAttributeMaxDynamicSharedMemorySize, SEARCH_SMEM);
    cudaFuncSetAttribute(gather_kernel, cudaFuncAttributeMaxDynamicSharedMemorySize, GATHER_SMEM);

    prep_wn_kernel<<<Dd, 128>>>(vin, gin, Cc, 0);
    prep_wn_kernel<<<Cc, 128>>>(vout, gout, Dd, 1);
    prep_cbinv_kernel<<<Kk, 128>>>(cb);
    ze_gemm_kernel<<<dim3(Ll/64, Dd/64, Nn), 128>>>(x, bin);
    wq_gemm_kernel<<<dim3(Kk/64, Cc/64), 128>>>(cb);
    search_kernel<<<Pp/64, 128, SEARCH_SMEM>>>(cb, out);
    gather_kernel<<<dim3(Ll/32, Nn), 256, GATHER_SMEM>>>(bout, out);
    finalize_kernel<<<1, 128>>>(out);
}